// round 2
// baseline (speedup 1.0000x reference)
#include <cuda_runtime.h>
#include <cstdint>

#define MAXDISP 48
#define DISP 49
#define GROUP 8
#define CPG 8
#define HH 96
#define WW 320
#define BB 2
#define EPSN 1e-5f
#define RPC 4            // h-rows per CTA
#define TPR 80           // threads per row = WW/4
#define CHW (HH*WW)

__device__ __forceinline__ uint32_t swz(uint32_t o) {
    // SW128-style XOR swizzle: bijective within 1 KB, keeps 16B alignment
    return o ^ ((o >> 3) & 0x70);
}

// One step of the disparity sweep. DM = d & 3 (compile-time) so the sliding
// register-window slot indices are static.
template<int DM>
__device__ __forceinline__ void step(int d,
                                     const float (&xn)[4][CPG],
                                     const float (&s_pad)[4],
                                     float (&Wn)[4][CPG],
                                     const char* rowp,
                                     float4* op, int w0) {
    float res[4];
#pragma unroll
    for (int i = 0; i < 4; i++) {
        const int slot = (i - DM) & 3;   // entry (w0+i-d) lives in slot (w0+i-d)&3
        float s = 0.f;
#pragma unroll
        for (int c = 0; c < CPG; c++)
            s += fabsf(xn[i][c] - Wn[slot][c]);
        res[i] = (w0 + i >= d) ? s : s_pad[i];
    }
    op[d * (CHW / 4)] = make_float4(res[0], res[1], res[2], res[3]);

    // fetch next window entry: e = w0 - d - 1 (clamped; unused lanes broadcast)
    const int slotn = (3 - DM) & 3;
    int en = w0 - d - 1;
    if (en < 0) en = 0;
    const float4 lo = *(const float4*)(rowp + swz((uint32_t)en * 32u));
    const float4 hi = *(const float4*)(rowp + swz((uint32_t)en * 32u + 16u));
    Wn[slotn][0] = lo.x; Wn[slotn][1] = lo.y; Wn[slotn][2] = lo.z; Wn[slotn][3] = lo.w;
    Wn[slotn][4] = hi.x; Wn[slotn][5] = hi.y; Wn[slotn][6] = hi.z; Wn[slotn][7] = hi.w;
}

__global__ __launch_bounds__(TPR * RPC, 2)
void cost_volume_kernel(const float* __restrict__ x,
                        const float* __restrict__ y,
                        float* __restrict__ out) {
    // per row: 320 entries x 32 B (8 ch), SW128-swizzled -> 10 KB; 4 rows = 40 KB
    __shared__ __align__(1024) char yns_raw[RPC * WW * 32];

    const int lx = threadIdx.x;            // 0..79
    const int r  = threadIdx.y;            // 0..3
    const int h  = blockIdx.x * RPC + r;
    const int g  = blockIdx.y;
    const int b  = blockIdx.z;
    const int w0 = lx * 4;

    char* rowp = yns_raw + r * (WW * 32);

    const float4* xp = (const float4*)(x + ((b * 64 + g * CPG) * HH + h) * WW) + lx;
    const float4* yp = (const float4*)(y + ((b * 64 + g * CPG) * HH + h) * WW) + lx;

    // load 8 channels x 4 w for both tensors (LDG.128, fully coalesced)
    float xn[4][CPG];
    float ynr[4][CPG];
#pragma unroll
    for (int c = 0; c < CPG; c++) {
        const float4 tx = xp[c * (CHW / 4)];
        const float4 ty = yp[c * (CHW / 4)];
        xn[0][c] = tx.x; xn[1][c] = tx.y; xn[2][c] = tx.z; xn[3][c] = tx.w;
        ynr[0][c] = ty.x; ynr[1][c] = ty.y; ynr[2][c] = ty.z; ynr[3][c] = ty.w;
    }

    // per-pixel group normalization (thread-local over 8 channels)
#pragma unroll
    for (int i = 0; i < 4; i++) {
        float sx = 0.f, sy = 0.f;
#pragma unroll
        for (int c = 0; c < CPG; c++) {
            sx += xn[i][c] * xn[i][c];
            sy += ynr[i][c] * ynr[i][c];
        }
        const float ix = 1.f / (sqrtf(sx) + EPSN);
        const float iy = 1.f / (sqrtf(sy) + EPSN);
#pragma unroll
        for (int c = 0; c < CPG; c++) {
            xn[i][c] *= ix;
            ynr[i][c] *= iy;
        }
    }

    // publish yn entries (32 B each) to swizzled smem
#pragma unroll
    for (int i = 0; i < 4; i++) {
        const uint32_t e = (uint32_t)(w0 + i) * 32u;
        *(float4*)(rowp + swz(e))       = make_float4(ynr[i][0], ynr[i][1], ynr[i][2], ynr[i][3]);
        *(float4*)(rowp + swz(e + 16u)) = make_float4(ynr[i][4], ynr[i][5], ynr[i][6], ynr[i][7]);
    }

    // zero-pad cost: sum |xn|
    float s_pad[4];
#pragma unroll
    for (int i = 0; i < 4; i++) {
        float s = 0.f;
#pragma unroll
        for (int c = 0; c < CPG; c++) s += fabsf(xn[i][c]);
        s_pad[i] = s;
    }

    // init sliding window: entries w0..w0+3 are this thread's own yn
    float Wn[4][CPG];
#pragma unroll
    for (int i = 0; i < 4; i++)
#pragma unroll
        for (int c = 0; c < CPG; c++)
            Wn[i][c] = ynr[i][c];   // entry w0+i -> slot (w0+i)&3 = i

    __syncthreads();

    float4* op = (float4*)(out + ((b * GROUP + g) * DISP * HH + h) * WW) + lx;

    // d = 0 uses the initial window
    step<0>(0, xn, s_pad, Wn, rowp, op, w0);
#pragma unroll 2
    for (int d4 = 1; d4 < 49; d4 += 4) {
        step<1>(d4 + 0, xn, s_pad, Wn, rowp, op, w0);
        step<2>(d4 + 1, xn, s_pad, Wn, rowp, op, w0);
        step<3>(d4 + 2, xn, s_pad, Wn, rowp, op, w0);
        step<0>(d4 + 3, xn, s_pad, Wn, rowp, op, w0);
    }
}

extern "C" void kernel_launch(void* const* d_in, const int* in_sizes, int n_in,
                              void* d_out, int out_size) {
    const float* x = (const float*)d_in[0];
    const float* y = (const float*)d_in[1];
    float* out = (float*)d_out;

    dim3 grid(HH / RPC, GROUP, BB);   // 24 x 8 x 2 = 384 CTAs
    dim3 block(TPR, RPC);             // 80 x 4 = 320 threads
    cost_volume_kernel<<<grid, block>>>(x, y, out);
}

// round 3
// speedup vs baseline: 1.2696x; 1.2696x over previous
#include <cuda_runtime.h>
#include <cstdint>

#define MAXDISP 48
#define DISP 49
#define GROUP 8
#define CPG 8
#define HH 96
#define WW 320
#define BB 2
#define EPSN 1e-5f
#define CHW (HH*WW)
#define PADE 49              // zero-filled entries for the left pad
#define NE (PADE + WW)       // 369 entries * 32 B = 11808 B

typedef unsigned long long u64;

__device__ __forceinline__ uint32_t swz(uint32_t o) {
    // toggles bits 4-6 from bits 7-9: bijective within each 128B block,
    // keeps 16B alignment, conflict-free for stride-64B lane patterns
    return o ^ ((o >> 3) & 0x70);
}
__device__ __forceinline__ u64 add2(u64 a, u64 b) {
    u64 r; asm("add.rn.f32x2 %0, %1, %2;" : "=l"(r) : "l"(a), "l"(b)); return r;
}
__device__ __forceinline__ u64 pack2(float lo, float hi) {
    u64 r; asm("mov.b64 %0, {%1, %2};" : "=l"(r) : "f"(lo), "f"(hi)); return r;
}
__device__ __forceinline__ float hsum(u64 a) {
    float lo, hi; asm("mov.b64 {%0, %1}, %2;" : "=f"(lo), "=f"(hi) : "l"(a));
    return lo + hi;
}

// One disparity step: 2 outputs per thread, sliding 2-entry register window.
// Window holds NEGATED yn, so diff = add2. DM = d & 1 (compile-time).
template<int DM>
__device__ __forceinline__ void step(int d, const u64 (&xn)[2][4], u64 (&Wn)[2][4],
                                     const char* rowp, float2* op, int w0) {
    const u64 M = 0x7fffffff7fffffffULL;
    float res[2];
#pragma unroll
    for (int p = 0; p < 2; p++) {
        const int s = DM ^ p;     // entry (w0+p-d) lives in slot (w0+p-d)&1 = (d+p)&1
        u64 a0 = add2(xn[p][0], Wn[s][0]) & M;
        u64 a1 = add2(xn[p][1], Wn[s][1]) & M;
        u64 a2 = add2(xn[p][2], Wn[s][2]) & M;
        u64 a3 = add2(xn[p][3], Wn[s][3]) & M;
        res[p] = hsum(add2(add2(a0, a1), add2(a2, a3)));
    }
    *op = make_float2(res[0], res[1]);

    // refill entry (w0 - d - 1) into slot DM^1 (its holder was just consumed)
    const uint32_t bo = (uint32_t)(w0 - d - 1 + PADE) * 32u;
    const ulonglong2 lo = *(const ulonglong2*)(rowp + swz(bo));
    const ulonglong2 hi = *(const ulonglong2*)(rowp + swz(bo + 16u));
    Wn[DM ^ 1][0] = lo.x; Wn[DM ^ 1][1] = lo.y;
    Wn[DM ^ 1][2] = hi.x; Wn[DM ^ 1][3] = hi.y;
}

__global__ __launch_bounds__(160, 6)
void cost_volume_kernel(const float* __restrict__ x,
                        const float* __restrict__ y,
                        float* __restrict__ out) {
    __shared__ __align__(128) char yns[NE * 32];

    const int lx = threadIdx.x;          // 0..159, owns w = 2lx, 2lx+1
    const int h = blockIdx.x;
    const int g = blockIdx.y;
    const int b = blockIdx.z;
    const int w0 = lx * 2;

    // zero-fill the pad region (entries -49..-1): pad cost emerges naturally
    if (lx < PADE) {
        const uint32_t bo = (uint32_t)lx * 32u;
        *(ulonglong2*)(yns + swz(bo))       = make_ulonglong2(0ULL, 0ULL);
        *(ulonglong2*)(yns + swz(bo + 16u)) = make_ulonglong2(0ULL, 0ULL);
    }

    const float2* xp = (const float2*)(x + ((b * 64 + g * CPG) * HH + h) * WW) + lx;
    const float2* yp = (const float2*)(y + ((b * 64 + g * CPG) * HH + h) * WW) + lx;

    float xv[2][CPG], yv[2][CPG];
    float sx[2] = {0.f, 0.f}, sy[2] = {0.f, 0.f};
#pragma unroll
    for (int c = 0; c < CPG; c++) {
        const float2 tx = xp[c * (CHW / 2)];
        const float2 ty = yp[c * (CHW / 2)];
        xv[0][c] = tx.x; xv[1][c] = tx.y;
        yv[0][c] = ty.x; yv[1][c] = ty.y;
        sx[0] += tx.x * tx.x; sx[1] += tx.y * tx.y;
        sy[0] += ty.x * ty.x; sy[1] += ty.y * ty.y;
    }

    u64 xn[2][4];
    u64 Wn[2][4];
#pragma unroll
    for (int p = 0; p < 2; p++) {
        const float ix =  1.f / (sqrtf(sx[p]) + EPSN);
        const float iy = -1.f / (sqrtf(sy[p]) + EPSN);   // NEGATED for add2-diff
#pragma unroll
        for (int q = 0; q < 4; q++) {
            xn[p][q] = pack2(xv[p][2 * q] * ix, xv[p][2 * q + 1] * ix);
            Wn[p][q] = pack2(yv[p][2 * q] * iy, yv[p][2 * q + 1] * iy);
        }
    }

    // publish -yn entries (entry w0+p -> slot p matches window init parity)
#pragma unroll
    for (int p = 0; p < 2; p++) {
        const uint32_t bo = (uint32_t)(w0 + p + PADE) * 32u;
        *(ulonglong2*)(yns + swz(bo))       = make_ulonglong2(Wn[p][0], Wn[p][1]);
        *(ulonglong2*)(yns + swz(bo + 16u)) = make_ulonglong2(Wn[p][2], Wn[p][3]);
    }
    __syncthreads();

    float2* op = (float2*)(out + ((b * GROUP + g) * DISP * HH + h) * WW) + lx;

    step<0>(0, xn, Wn, yns, op, w0); op += CHW / 2;
#pragma unroll 4
    for (int d = 1; d < DISP; d += 2) {
        step<1>(d,     xn, Wn, yns, op, w0); op += CHW / 2;
        step<0>(d + 1, xn, Wn, yns, op, w0); op += CHW / 2;
    }
}

extern "C" void kernel_launch(void* const* d_in, const int* in_sizes, int n_in,
                              void* d_out, int out_size) {
    const float* x = (const float*)d_in[0];
    const float* y = (const float*)d_in[1];
    float* out = (float*)d_out;

    dim3 grid(HH, GROUP, BB);   // 96 x 8 x 2 = 1536 CTAs
    dim3 block(160);            // 5 full warps, 2 w-columns per thread
    cost_volume_kernel<<<grid, block>>>(x, y, out);
}